// round 2
// baseline (speedup 1.0000x reference)
#include <cuda_runtime.h>
#include <mma.h>
#include <math.h>
#include <stdint.h>

using namespace nvcuda;

// Problem shape (fixed by the dataset)
#define TOK 8192      // B*N = 4*2048 tokens
#define CH  1024      // C
#define HID 4096      // H = 4C

// ---------------- scratch (static device globals; no allocation allowed) ----
__device__ float g_h  [TOK * CH];            // ln1(x)
__device__ float g_f  [TOK * CH];            // real(FFT) = h @ cos
__device__ float g_x1 [TOK * CH];            // x + lnf(f)
__device__ float g_h2 [TOK * CH];            // ln2(x1)
__device__ float g_m  [(size_t)TOK * HID];   // gelu(h2@w1+b1)
__device__ float g_cos[CH * CH];             // cosine transform matrix

// ---------------- helpers ---------------------------------------------------
__device__ __forceinline__ float to_tf32(float x) {
    uint32_t r;
    asm("cvt.rna.tf32.f32 %0, %1;" : "=r"(r) : "f"(x));  // tf32 dest must be b32
    return __uint_as_float(r);
}

// ---------------- cos matrix fill: cos(2*pi*k*n/1024), exact integer mod ----
__global__ void fill_cos_kernel() {
    int idx = blockIdx.x * blockDim.x + threadIdx.x;   // 1M threads
    int k = idx >> 10;
    int n = idx & 1023;
    int p = (k * n) & 1023;                            // exact argument reduction
    g_cos[idx] = cosf((float)p * 6.135923151542565e-3f);  // 2*pi/1024
}

// ---------------- LayerNorm over C=1024, one block (256 thr) per token ------
__global__ void ln_kernel(const float* __restrict__ in,
                          const float* __restrict__ g,
                          const float* __restrict__ b,
                          float* __restrict__ out) {
    __shared__ float sb[16];
    int row = blockIdx.x, t = threadIdx.x;
    float4 v = ((const float4*)(in + (size_t)row * CH))[t];
    float s = v.x + v.y + v.z + v.w;
    float q = v.x*v.x + v.y*v.y + v.z*v.z + v.w*v.w;
    #pragma unroll
    for (int o = 16; o; o >>= 1) {
        s += __shfl_xor_sync(~0u, s, o);
        q += __shfl_xor_sync(~0u, q, o);
    }
    if ((t & 31) == 0) { sb[t >> 5] = s; sb[8 + (t >> 5)] = q; }
    __syncthreads();
    s = 0.f; q = 0.f;
    #pragma unroll
    for (int i = 0; i < 8; i++) { s += sb[i]; q += sb[8 + i]; }
    float mu = s * (1.0f / CH);
    float rs = rsqrtf(q * (1.0f / CH) - mu * mu + 1e-5f);
    float4 gv = ((const float4*)g)[t];
    float4 bv = ((const float4*)b)[t];
    float4 o;
    o.x = (v.x - mu) * rs * gv.x + bv.x;
    o.y = (v.y - mu) * rs * gv.y + bv.y;
    o.z = (v.z - mu) * rs * gv.z + bv.z;
    o.w = (v.w - mu) * rs * gv.w + bv.w;
    ((float4*)(out + (size_t)row * CH))[t] = o;
}

// --------- fused: x1 = x + lnf(f);  h2 = ln2(x1)  (one block per token) -----
__global__ void fuse2_kernel(const float* __restrict__ x,
                             const float* __restrict__ lnfg, const float* __restrict__ lnfb,
                             const float* __restrict__ ln2g, const float* __restrict__ ln2b) {
    __shared__ float sb[16];
    int row = blockIdx.x, t = threadIdx.x;

    // ---- pass 1: LN(f) ----
    float4 fv = ((const float4*)(g_f + (size_t)row * CH))[t];
    float s = fv.x + fv.y + fv.z + fv.w;
    float q = fv.x*fv.x + fv.y*fv.y + fv.z*fv.z + fv.w*fv.w;
    #pragma unroll
    for (int o = 16; o; o >>= 1) {
        s += __shfl_xor_sync(~0u, s, o);
        q += __shfl_xor_sync(~0u, q, o);
    }
    if ((t & 31) == 0) { sb[t >> 5] = s; sb[8 + (t >> 5)] = q; }
    __syncthreads();
    s = 0.f; q = 0.f;
    #pragma unroll
    for (int i = 0; i < 8; i++) { s += sb[i]; q += sb[8 + i]; }
    float mu1 = s * (1.0f / CH);
    float rs1 = rsqrtf(q * (1.0f / CH) - mu1 * mu1 + 1e-5f);

    float4 xv  = ((const float4*)(x + (size_t)row * CH))[t];
    float4 g1  = ((const float4*)lnfg)[t];
    float4 b1v = ((const float4*)lnfb)[t];
    float4 x1v;
    x1v.x = xv.x + (fv.x - mu1) * rs1 * g1.x + b1v.x;
    x1v.y = xv.y + (fv.y - mu1) * rs1 * g1.y + b1v.y;
    x1v.z = xv.z + (fv.z - mu1) * rs1 * g1.z + b1v.z;
    x1v.w = xv.w + (fv.w - mu1) * rs1 * g1.w + b1v.w;
    ((float4*)(g_x1 + (size_t)row * CH))[t] = x1v;

    // ---- pass 2: LN(x1) ----
    __syncthreads();   // protect sb reuse
    s = x1v.x + x1v.y + x1v.z + x1v.w;
    q = x1v.x*x1v.x + x1v.y*x1v.y + x1v.z*x1v.z + x1v.w*x1v.w;
    #pragma unroll
    for (int o = 16; o; o >>= 1) {
        s += __shfl_xor_sync(~0u, s, o);
        q += __shfl_xor_sync(~0u, q, o);
    }
    if ((t & 31) == 0) { sb[t >> 5] = s; sb[8 + (t >> 5)] = q; }
    __syncthreads();
    s = 0.f; q = 0.f;
    #pragma unroll
    for (int i = 0; i < 8; i++) { s += sb[i]; q += sb[8 + i]; }
    float mu2 = s * (1.0f / CH);
    float rs2 = rsqrtf(q * (1.0f / CH) - mu2 * mu2 + 1e-5f);

    float4 g2  = ((const float4*)ln2g)[t];
    float4 b2v = ((const float4*)ln2b)[t];
    float4 h2v;
    h2v.x = (x1v.x - mu2) * rs2 * g2.x + b2v.x;
    h2v.y = (x1v.y - mu2) * rs2 * g2.y + b2v.y;
    h2v.z = (x1v.z - mu2) * rs2 * g2.z + b2v.z;
    h2v.w = (x1v.w - mu2) * rs2 * g2.w + b2v.w;
    ((float4*)(g_h2 + (size_t)row * CH))[t] = h2v;
}

// ---------------- TF32 wmma GEMM: C = epi(A[MxK] @ B[KxN]) ------------------
// EPI: 0 = plain store   1 = gelu(.+bias)   2 = .+bias+residual
template <int EPI>
__global__ void __launch_bounds__(256)
gemm_tf32(const float* __restrict__ A, const float* __restrict__ B,
          float* __restrict__ Cout,
          const float* __restrict__ bias, const float* __restrict__ resid,
          int M, int N, int K) {
    constexpr int BM = 128, BN = 128, BK = 16;
    constexpr int SA = BK + 4;   // 20 floats (80B, 16B-multiple)
    constexpr int SB = BN + 4;   // 132 floats (528B, 16B-multiple)

    __shared__ float As[BM * SA];
    __shared__ float Bs[BK * SB];
    __shared__ float ebuf[8][256];

    int tid  = threadIdx.x;
    int warp = tid >> 5, lane = tid & 31;
    int wm = warp & 1;        // 2 warps across M (64 rows each)
    int wn = warp >> 1;       // 4 warps across N (32 cols each)
    int bm = blockIdx.y * BM, bn = blockIdx.x * BN;

    wmma::fragment<wmma::accumulator, 16, 16, 8, float> acc[4][2];
    #pragma unroll
    for (int i = 0; i < 4; i++)
        #pragma unroll
        for (int j = 0; j < 2; j++) wmma::fill_fragment(acc[i][j], 0.0f);

    int ar = tid >> 2, ac = (tid & 3) << 2;    // A: 64 rows x 16 cols per pass
    int br = tid >> 5, bc = (tid & 31) << 2;   // B: 8 rows x 128 cols per pass

    for (int kb = 0; kb < K; kb += BK) {
        #pragma unroll
        for (int rr = 0; rr < BM; rr += 64) {
            float4 v = *(const float4*)(A + (size_t)(bm + ar + rr) * K + kb + ac);
            float* d = &As[(ar + rr) * SA + ac];
            d[0] = to_tf32(v.x); d[1] = to_tf32(v.y);
            d[2] = to_tf32(v.z); d[3] = to_tf32(v.w);
        }
        #pragma unroll
        for (int rr = 0; rr < BK; rr += 8) {
            float4 v = *(const float4*)(B + (size_t)(kb + br + rr) * N + bn + bc);
            float* d = &Bs[(br + rr) * SB + bc];
            d[0] = to_tf32(v.x); d[1] = to_tf32(v.y);
            d[2] = to_tf32(v.z); d[3] = to_tf32(v.w);
        }
        __syncthreads();

        #pragma unroll
        for (int kk = 0; kk < BK; kk += 8) {
            wmma::fragment<wmma::matrix_a, 16, 16, 8, wmma::precision::tf32, wmma::row_major> af[4];
            wmma::fragment<wmma::matrix_b, 16, 16, 8, wmma::precision::tf32, wmma::row_major> bf[2];
            #pragma unroll
            for (int i = 0; i < 4; i++)
                wmma::load_matrix_sync(af[i], &As[(wm * 64 + i * 16) * SA + kk], SA);
            #pragma unroll
            for (int j = 0; j < 2; j++)
                wmma::load_matrix_sync(bf[j], &Bs[kk * SB + wn * 32 + j * 16], SB);
            #pragma unroll
            for (int i = 0; i < 4; i++)
                #pragma unroll
                for (int j = 0; j < 2; j++)
                    wmma::mma_sync(acc[i][j], af[i], bf[j], acc[i][j]);
        }
        __syncthreads();
    }

    // epilogue via per-warp smem staging
    #pragma unroll
    for (int i = 0; i < 4; i++) {
        #pragma unroll
        for (int j = 0; j < 2; j++) {
            wmma::store_matrix_sync(ebuf[warp], acc[i][j], 16, wmma::mem_row_major);
            __syncwarp();
            int gr0 = bm + wm * 64 + i * 16;
            int gc0 = bn + wn * 32 + j * 16;
            #pragma unroll
            for (int e = lane; e < 256; e += 32) {
                int r = e >> 4, cc = e & 15;
                float v = ebuf[warp][e];
                int gr = gr0 + r, gc = gc0 + cc;
                if (EPI == 1) {
                    v += bias[gc];
                    v = 0.5f * v * (1.0f + erff(v * 0.70710678118654752f));  // exact GELU
                } else if (EPI == 2) {
                    v += bias[gc] + resid[(size_t)gr * N + gc];
                }
                Cout[(size_t)gr * N + gc] = v;
            }
            __syncwarp();
        }
    }
}

// ---------------- entry -----------------------------------------------------
extern "C" void kernel_launch(void* const* d_in, const int* in_sizes, int n_in,
                              void* d_out, int out_size) {
    const float* x    = (const float*)d_in[0];
    const float* ln1g = (const float*)d_in[1];
    const float* ln1b = (const float*)d_in[2];
    const float* lnfg = (const float*)d_in[3];
    const float* lnfb = (const float*)d_in[4];
    const float* ln2g = (const float*)d_in[5];
    const float* ln2b = (const float*)d_in[6];
    const float* w1   = (const float*)d_in[7];
    const float* b1   = (const float*)d_in[8];
    const float* w2   = (const float*)d_in[9];
    const float* b2   = (const float*)d_in[10];
    float* out = (float*)d_out;

    float *ph, *pf, *px1, *ph2, *pm, *pcos;
    cudaGetSymbolAddress((void**)&ph,   g_h);
    cudaGetSymbolAddress((void**)&pf,   g_f);
    cudaGetSymbolAddress((void**)&px1,  g_x1);
    cudaGetSymbolAddress((void**)&ph2,  g_h2);
    cudaGetSymbolAddress((void**)&pm,   g_m);
    cudaGetSymbolAddress((void**)&pcos, g_cos);

    // 1. cosine transform matrix (deterministic; rebuilt every call)
    fill_cos_kernel<<<1024, 1024>>>();
    // 2. h = ln1(x)
    ln_kernel<<<TOK, 256>>>(x, ln1g, ln1b, ph);
    // 3. f = h @ cos    [8192,1024] @ [1024,1024]
    gemm_tf32<0><<<dim3(CH / 128, TOK / 128), 256>>>(ph, pcos, pf,
                                                     nullptr, nullptr, TOK, CH, CH);
    // 4. x1 = x + lnf(f); h2 = ln2(x1)
    fuse2_kernel<<<TOK, 256>>>(x, lnfg, lnfb, ln2g, ln2b);
    // 5. m = gelu(h2 @ w1 + b1)   [8192,1024] @ [1024,4096]
    gemm_tf32<1><<<dim3(HID / 128, TOK / 128), 256>>>(ph2, w1, pm,
                                                      b1, nullptr, TOK, HID, CH);
    // 6. out = x1 + m @ w2 + b2   [8192,4096] @ [4096,1024]
    gemm_tf32<2><<<dim3(CH / 128, TOK / 128), 256>>>(pm, w2, out,
                                                     b2, px1, TOK, CH, HID);
}

// round 5
// speedup vs baseline: 1.0800x; 1.0800x over previous
#include <cuda_runtime.h>
#include <mma.h>
#include <math.h>
#include <stdint.h>

using namespace nvcuda;

#define TOK 8192      // B*N tokens
#define CH  1024      // C
#define HID 4096      // H = 4C

// ---------------- scratch (static device globals) ---------------------------
__device__ float g_h  [TOK * CH];            // ln1(x), tf32-rounded
__device__ float g_f  [TOK * CH];            // real(FFT)
__device__ float g_x1 [TOK * CH];            // x + lnf(f), full fp32
__device__ float g_h2 [TOK * CH];            // ln2(x1), tf32-rounded
__device__ float g_m  [(size_t)TOK * HID];   // gelu(...), tf32-rounded
__device__ float g_cos[CH * CH];             // cosine matrix, tf32-rounded
__device__ float g_w1r[CH * HID];            // tf32-rounded w1
__device__ float g_w2r[HID * CH];            // tf32-rounded w2

// ---------------- helpers ---------------------------------------------------
__device__ __forceinline__ float to_tf32(float x) {
    uint32_t r;
    asm("cvt.rna.tf32.f32 %0, %1;" : "=r"(r) : "f"(x));
    return __uint_as_float(r);
}
__device__ __forceinline__ void cp16(float* dst_smem, const float* src) {
    uint32_t d = (uint32_t)__cvta_generic_to_shared(dst_smem);
    asm volatile("cp.async.cg.shared.global [%0], [%1], 16;\n" :: "r"(d), "l"(src));
}
#define CP_COMMIT() asm volatile("cp.async.commit_group;\n" ::: "memory")

// ---------------- cos matrix: cos(2*pi*k*n/1024), exact integer mod ---------
__global__ void fill_cos_kernel() {
    int idx = blockIdx.x * blockDim.x + threadIdx.x;
    int k = idx >> 10, n = idx & 1023;
    int p = (k * n) & 1023;
    g_cos[idx] = to_tf32(cosf((float)p * 6.135923151542565e-3f));
}

// ---------------- round a tensor to tf32 ------------------------------------
__global__ void round_kernel(const float* __restrict__ in, float* __restrict__ out) {
    int i = blockIdx.x * blockDim.x + threadIdx.x;
    float4 v = ((const float4*)in)[i];
    v.x = to_tf32(v.x); v.y = to_tf32(v.y); v.z = to_tf32(v.z); v.w = to_tf32(v.w);
    ((float4*)out)[i] = v;
}

// ---------------- LayerNorm, one block (256 thr) per token, tf32 store ------
__global__ void ln_kernel(const float* __restrict__ in,
                          const float* __restrict__ g,
                          const float* __restrict__ b,
                          float* __restrict__ out) {
    __shared__ float sb[16];
    int row = blockIdx.x, t = threadIdx.x;
    float4 v = ((const float4*)(in + (size_t)row * CH))[t];
    float s = v.x + v.y + v.z + v.w;
    float q = v.x*v.x + v.y*v.y + v.z*v.z + v.w*v.w;
    #pragma unroll
    for (int o = 16; o; o >>= 1) {
        s += __shfl_xor_sync(~0u, s, o);
        q += __shfl_xor_sync(~0u, q, o);
    }
    if ((t & 31) == 0) { sb[t >> 5] = s; sb[8 + (t >> 5)] = q; }
    __syncthreads();
    s = 0.f; q = 0.f;
    #pragma unroll
    for (int i = 0; i < 8; i++) { s += sb[i]; q += sb[8 + i]; }
    float mu = s * (1.0f / CH);
    float rs = rsqrtf(q * (1.0f / CH) - mu * mu + 1e-5f);
    float4 gv = ((const float4*)g)[t];
    float4 bv = ((const float4*)b)[t];
    float4 o;
    o.x = to_tf32((v.x - mu) * rs * gv.x + bv.x);
    o.y = to_tf32((v.y - mu) * rs * gv.y + bv.y);
    o.z = to_tf32((v.z - mu) * rs * gv.z + bv.z);
    o.w = to_tf32((v.w - mu) * rs * gv.w + bv.w);
    ((float4*)(out + (size_t)row * CH))[t] = o;
}

// --------- fused: x1 = x + lnf(f);  h2 = tf32(ln2(x1)) ----------------------
__global__ void fuse2_kernel(const float* __restrict__ x,
                             const float* __restrict__ lnfg, const float* __restrict__ lnfb,
                             const float* __restrict__ ln2g, const float* __restrict__ ln2b) {
    __shared__ float sb[16];
    int row = blockIdx.x, t = threadIdx.x;

    float4 fv = ((const float4*)(g_f + (size_t)row * CH))[t];
    float s = fv.x + fv.y + fv.z + fv.w;
    float q = fv.x*fv.x + fv.y*fv.y + fv.z*fv.z + fv.w*fv.w;
    #pragma unroll
    for (int o = 16; o; o >>= 1) {
        s += __shfl_xor_sync(~0u, s, o);
        q += __shfl_xor_sync(~0u, q, o);
    }
    if ((t & 31) == 0) { sb[t >> 5] = s; sb[8 + (t >> 5)] = q; }
    __syncthreads();
    s = 0.f; q = 0.f;
    #pragma unroll
    for (int i = 0; i < 8; i++) { s += sb[i]; q += sb[8 + i]; }
    float mu1 = s * (1.0f / CH);
    float rs1 = rsqrtf(q * (1.0f / CH) - mu1 * mu1 + 1e-5f);

    float4 xv  = ((const float4*)(x + (size_t)row * CH))[t];
    float4 g1  = ((const float4*)lnfg)[t];
    float4 b1v = ((const float4*)lnfb)[t];
    float4 x1v;
    x1v.x = xv.x + (fv.x - mu1) * rs1 * g1.x + b1v.x;
    x1v.y = xv.y + (fv.y - mu1) * rs1 * g1.y + b1v.y;
    x1v.z = xv.z + (fv.z - mu1) * rs1 * g1.z + b1v.z;
    x1v.w = xv.w + (fv.w - mu1) * rs1 * g1.w + b1v.w;
    ((float4*)(g_x1 + (size_t)row * CH))[t] = x1v;

    __syncthreads();
    s = x1v.x + x1v.y + x1v.z + x1v.w;
    q = x1v.x*x1v.x + x1v.y*x1v.y + x1v.z*x1v.z + x1v.w*x1v.w;
    #pragma unroll
    for (int o = 16; o; o >>= 1) {
        s += __shfl_xor_sync(~0u, s, o);
        q += __shfl_xor_sync(~0u, q, o);
    }
    if ((t & 31) == 0) { sb[t >> 5] = s; sb[8 + (t >> 5)] = q; }
    __syncthreads();
    s = 0.f; q = 0.f;
    #pragma unroll
    for (int i = 0; i < 8; i++) { s += sb[i]; q += sb[8 + i]; }
    float mu2 = s * (1.0f / CH);
    float rs2 = rsqrtf(q * (1.0f / CH) - mu2 * mu2 + 1e-5f);

    float4 g2  = ((const float4*)ln2g)[t];
    float4 b2v = ((const float4*)ln2b)[t];
    float4 h2v;
    h2v.x = to_tf32((x1v.x - mu2) * rs2 * g2.x + b2v.x);
    h2v.y = to_tf32((x1v.y - mu2) * rs2 * g2.y + b2v.y);
    h2v.z = to_tf32((x1v.z - mu2) * rs2 * g2.z + b2v.z);
    h2v.w = to_tf32((x1v.w - mu2) * rs2 * g2.w + b2v.w);
    ((float4*)(g_h2 + (size_t)row * CH))[t] = h2v;
}

// ------- pipelined TF32 wmma GEMM: C = epi(A[MxK] @ B[KxN]) -----------------
// Inputs must already be tf32-rounded. 3-stage cp.async, 128x128x32 tiles.
// Canonical group accounting: every commit_group has real cp.asyncs; the tail
// drains with wait_group 1 / wait_group 0 (never an empty commit).
// EPI: 0 = plain store   1 = tf32(gelu(.+bias))   2 = .+bias+residual
template <int EPI>
__global__ void __launch_bounds__(256)
gemm_tf32(const float* __restrict__ A, const float* __restrict__ B,
          float* __restrict__ Cout,
          const float* __restrict__ bias, const float* __restrict__ resid,
          int M, int N, int K) {
    constexpr int BM = 128, BN = 128, BK = 32, STG = 3;
    constexpr int SA = BK + 4;   // 36 floats/row
    constexpr int SB = BN + 4;   // 132 floats/row
    constexpr int ASZ = BM * SA, BSZ = BK * SB;

    extern __shared__ float smem[];
    float* As = smem;             // STG * ASZ
    float* Bs = smem + STG * ASZ; // STG * BSZ
    __shared__ float ebuf[8][256];

    int tid  = threadIdx.x;
    int warp = tid >> 5, lane = tid & 31;
    int wm = warp & 1;            // 2 warps over M (64 rows each)
    int wn = warp >> 1;           // 4 warps over N (32 cols each)
    int bm = blockIdx.y * BM, bn = blockIdx.x * BN;

    wmma::fragment<wmma::accumulator, 16, 16, 8, float> acc[4][2];
    #pragma unroll
    for (int i = 0; i < 4; i++)
        #pragma unroll
        for (int j = 0; j < 2; j++) wmma::fill_fragment(acc[i][j], 0.0f);

    auto loadStage = [&](int kt, int slot) {
        int kb = kt * BK;
        float* as = As + slot * ASZ;
        float* bs = Bs + slot * BSZ;
        #pragma unroll
        for (int i = 0; i < 4; i++) {          // A: 1024 float4 / 256 thr
            int f = tid + i * 256;
            int r = f >> 3, c4 = (f & 7) << 2;
            cp16(as + r * SA + c4, A + (size_t)(bm + r) * K + kb + c4);
        }
        #pragma unroll
        for (int i = 0; i < 4; i++) {          // B: 1024 float4 / 256 thr
            int f = tid + i * 256;
            int r = f >> 5, c4 = (f & 31) << 2;
            cp16(bs + r * SB + c4, B + (size_t)(kb + r) * N + bn + c4);
        }
    };

    int NT = K / BK;                 // >= 32 for all our shapes
    loadStage(0, 0); CP_COMMIT();
    loadStage(1, 1); CP_COMMIT();

    for (int kt = 0; kt < NT; kt++) {
        if (kt + 2 < NT) {
            loadStage(kt + 2, (kt + 2) % STG);
            CP_COMMIT();
            asm volatile("cp.async.wait_group 2;\n" ::: "memory");
        } else if (kt + 1 < NT) {
            asm volatile("cp.async.wait_group 1;\n" ::: "memory");
        } else {
            asm volatile("cp.async.wait_group 0;\n" ::: "memory");
        }
        __syncthreads();

        float* as = As + (kt % STG) * ASZ;
        float* bs = Bs + (kt % STG) * BSZ;
        #pragma unroll
        for (int kk = 0; kk < BK; kk += 8) {
            wmma::fragment<wmma::matrix_a, 16, 16, 8, wmma::precision::tf32, wmma::row_major> af[4];
            wmma::fragment<wmma::matrix_b, 16, 16, 8, wmma::precision::tf32, wmma::row_major> bf[2];
            #pragma unroll
            for (int i = 0; i < 4; i++)
                wmma::load_matrix_sync(af[i], &as[(wm * 64 + i * 16) * SA + kk], SA);
            #pragma unroll
            for (int j = 0; j < 2; j++)
                wmma::load_matrix_sync(bf[j], &bs[kk * SB + wn * 32 + j * 16], SB);
            #pragma unroll
            for (int i = 0; i < 4; i++)
                #pragma unroll
                for (int j = 0; j < 2; j++)
                    wmma::mma_sync(acc[i][j], af[i], bf[j], acc[i][j]);
        }
        __syncthreads();
    }

    // epilogue via per-warp smem staging
    #pragma unroll
    for (int i = 0; i < 4; i++) {
        #pragma unroll
        for (int j = 0; j < 2; j++) {
            wmma::store_matrix_sync(ebuf[warp], acc[i][j], 16, wmma::mem_row_major);
            __syncwarp();
            int gr0 = bm + wm * 64 + i * 16;
            int gc0 = bn + wn * 32 + j * 16;
            #pragma unroll
            for (int e = lane; e < 256; e += 32) {
                int r = e >> 4, cc = e & 15;
                float v = ebuf[warp][e];
                int gr = gr0 + r, gc = gc0 + cc;
                if (EPI == 1) {
                    v += bias[gc];
                    v = 0.5f * v * (1.0f + erff(v * 0.70710678118654752f));
                    v = to_tf32(v);            // next GEMM's operand
                } else if (EPI == 2) {
                    v += bias[gc] + resid[(size_t)gr * N + gc];
                }
                Cout[(size_t)gr * N + gc] = v;
            }
            __syncwarp();
        }
    }
}

// ---------------- entry -----------------------------------------------------
extern "C" void kernel_launch(void* const* d_in, const int* in_sizes, int n_in,
                              void* d_out, int out_size) {
    const float* x    = (const float*)d_in[0];
    const float* ln1g = (const float*)d_in[1];
    const float* ln1b = (const float*)d_in[2];
    const float* lnfg = (const float*)d_in[3];
    const float* lnfb = (const float*)d_in[4];
    const float* ln2g = (const float*)d_in[5];
    const float* ln2b = (const float*)d_in[6];
    const float* w1   = (const float*)d_in[7];
    const float* b1   = (const float*)d_in[8];
    const float* w2   = (const float*)d_in[9];
    const float* b2   = (const float*)d_in[10];
    float* out = (float*)d_out;

    float *ph, *pf, *px1, *ph2, *pm, *pcos, *pw1r, *pw2r;
    cudaGetSymbolAddress((void**)&ph,   g_h);
    cudaGetSymbolAddress((void**)&pf,   g_f);
    cudaGetSymbolAddress((void**)&px1,  g_x1);
    cudaGetSymbolAddress((void**)&ph2,  g_h2);
    cudaGetSymbolAddress((void**)&pm,   g_m);
    cudaGetSymbolAddress((void**)&pcos, g_cos);
    cudaGetSymbolAddress((void**)&pw1r, g_w1r);
    cudaGetSymbolAddress((void**)&pw2r, g_w2r);

    constexpr int SMEM = (3 * 128 * 36 + 3 * 32 * 132) * 4;  // 105984 B
    cudaFuncSetAttribute(gemm_tf32<0>, cudaFuncAttributeMaxDynamicSharedMemorySize, SMEM);
    cudaFuncSetAttribute(gemm_tf32<1>, cudaFuncAttributeMaxDynamicSharedMemorySize, SMEM);
    cudaFuncSetAttribute(gemm_tf32<2>, cudaFuncAttributeMaxDynamicSharedMemorySize, SMEM);

    // 1. constants / operand rounding
    fill_cos_kernel<<<1024, 1024>>>();
    round_kernel<<<(CH * HID / 4) / 256, 256>>>(w1, pw1r);
    round_kernel<<<(HID * CH / 4) / 256, 256>>>(w2, pw2r);
    // 2. h = tf32(ln1(x))
    ln_kernel<<<TOK, 256>>>(x, ln1g, ln1b, ph);
    // 3. f = h @ cos
    gemm_tf32<0><<<dim3(CH / 128, TOK / 128), 256, SMEM>>>(ph, pcos, pf,
                                                           nullptr, nullptr, TOK, CH, CH);
    // 4. x1 = x + lnf(f); h2 = tf32(ln2(x1))
    fuse2_kernel<<<TOK, 256>>>(x, lnfg, lnfb, ln2g, ln2b);
    // 5. m = tf32(gelu(h2 @ w1 + b1))
    gemm_tf32<1><<<dim3(HID / 128, TOK / 128), 256, SMEM>>>(ph2, pw1r, pm,
                                                            b1, nullptr, TOK, HID, CH);
    // 6. out = x1 + m @ w2 + b2
    gemm_tf32<2><<<dim3(CH / 128, TOK / 128), 256, SMEM>>>(pm, pw2r, out,
                                                           b2, px1, TOK, CH, HID);
}

// round 7
// speedup vs baseline: 5.5969x; 5.1822x over previous
#include <cuda_runtime.h>
#include <cuda_fp16.h>
#include <math.h>
#include <stdint.h>

#define TOK 8192      // B*N tokens
#define CH  1024
#define HID 4096

// ---------------- scratch ----------------------------------------------------
__device__ __half g_h  [TOK * CH];            // ln1(x), fp16
__device__ float  g_f  [TOK * CH];            // real(FFT), fp32
__device__ float  g_x1 [TOK * CH];            // x + lnf(f), fp32
__device__ __half g_h2 [TOK * CH];            // ln2(x1), fp16
__device__ __half g_m  [(size_t)TOK * HID];   // gelu(...), fp16
__device__ __half g_cosh[CH * CH];            // cosine matrix [N][K], fp16 (symmetric)
__device__ __half g_w1t[(size_t)HID * CH];    // w1^T  [N=HID][K=CH], fp16
__device__ __half g_w2t[(size_t)CH * HID];    // w2^T  [N=CH][K=HID], fp16

// ---------------- helpers ----------------------------------------------------
__device__ __forceinline__ uint32_t smem_u32(const void* p) {
    uint32_t a;
    asm("{ .reg .u64 t; cvta.to.shared.u64 t, %1; cvt.u32.u64 %0, t; }" : "=r"(a) : "l"(p));
    return a;
}
__device__ __forceinline__ void cp16(uint32_t dst, const void* src) {
    asm volatile("cp.async.cg.shared.global [%0], [%1], 16;" :: "r"(dst), "l"(src));
}
#define CP_COMMIT() asm volatile("cp.async.commit_group;" ::: "memory")
#define SW128(o) ((o) ^ (((o) >> 3) & 0x70))

__device__ __forceinline__ void ldsm4(uint32_t* r, uint32_t a) {
    asm volatile("ldmatrix.sync.aligned.m8n8.x4.shared.b16 {%0,%1,%2,%3}, [%4];"
                 : "=r"(r[0]), "=r"(r[1]), "=r"(r[2]), "=r"(r[3]) : "r"(a));
}
__device__ __forceinline__ void ldsm2(uint32_t* r, uint32_t a) {
    asm volatile("ldmatrix.sync.aligned.m8n8.x2.shared.b16 {%0,%1}, [%2];"
                 : "=r"(r[0]), "=r"(r[1]) : "r"(a));
}
__device__ __forceinline__ void mma16816(float* d, const uint32_t* a, const uint32_t* b) {
    asm volatile("mma.sync.aligned.m16n8k16.row.col.f32.f16.f16.f32 "
                 "{%0,%1,%2,%3}, {%4,%5,%6,%7}, {%8,%9}, {%0,%1,%2,%3};"
                 : "+f"(d[0]), "+f"(d[1]), "+f"(d[2]), "+f"(d[3])
                 : "r"(a[0]), "r"(a[1]), "r"(a[2]), "r"(a[3]), "r"(b[0]), "r"(b[1]));
}

// ---------------- small kernels ----------------------------------------------
__global__ void fill_cos_kernel() {
    int idx = blockIdx.x * blockDim.x + threadIdx.x;
    int k = idx >> 10, n = idx & 1023;
    int p = (k * n) & 1023;
    g_cosh[idx] = __float2half_rn(cosf((float)p * 6.135923151542565e-3f));
}

// out[C][R] = fp16(in[R][C])
__global__ void transpose_h(const float* __restrict__ in, __half* __restrict__ out,
                            int R, int C) {
    __shared__ float t[32][33];
    int bx = blockIdx.x * 32, by = blockIdx.y * 32;
    #pragma unroll
    for (int j = 0; j < 32; j += 8)
        t[threadIdx.y + j][threadIdx.x] = in[(size_t)(by + threadIdx.y + j) * C + bx + threadIdx.x];
    __syncthreads();
    #pragma unroll
    for (int j = 0; j < 32; j += 8)
        out[(size_t)(bx + threadIdx.y + j) * R + by + threadIdx.x] =
            __float2half_rn(t[threadIdx.x][threadIdx.y + j]);
}

__global__ void ln_kernel(const float* __restrict__ in, const float* __restrict__ g,
                          const float* __restrict__ b, __half* __restrict__ out) {
    __shared__ float sb[16];
    int row = blockIdx.x, t = threadIdx.x;
    float4 v = ((const float4*)(in + (size_t)row * CH))[t];
    float s = v.x + v.y + v.z + v.w;
    float q = v.x*v.x + v.y*v.y + v.z*v.z + v.w*v.w;
    #pragma unroll
    for (int o = 16; o; o >>= 1) { s += __shfl_xor_sync(~0u, s, o); q += __shfl_xor_sync(~0u, q, o); }
    if ((t & 31) == 0) { sb[t >> 5] = s; sb[8 + (t >> 5)] = q; }
    __syncthreads();
    s = 0.f; q = 0.f;
    #pragma unroll
    for (int i = 0; i < 8; i++) { s += sb[i]; q += sb[8 + i]; }
    float mu = s * (1.0f / CH);
    float rs = rsqrtf(q * (1.0f / CH) - mu * mu + 1e-5f);
    float4 gv = ((const float4*)g)[t];
    float4 bv = ((const float4*)b)[t];
    __half2 p0, p1;
    p0.x = __float2half_rn((v.x - mu) * rs * gv.x + bv.x);
    p0.y = __float2half_rn((v.y - mu) * rs * gv.y + bv.y);
    p1.x = __float2half_rn((v.z - mu) * rs * gv.z + bv.z);
    p1.y = __float2half_rn((v.w - mu) * rs * gv.w + bv.w);
    __half2* dst = (__half2*)(out + (size_t)row * CH);
    dst[2 * t] = p0; dst[2 * t + 1] = p1;
}

// x1 = x + lnf(f) [fp32]; h2 = fp16(ln2(x1))
__global__ void fuse2_kernel(const float* __restrict__ x,
                             const float* __restrict__ lnfg, const float* __restrict__ lnfb,
                             const float* __restrict__ ln2g, const float* __restrict__ ln2b) {
    __shared__ float sb[16];
    int row = blockIdx.x, t = threadIdx.x;
    float4 fv = ((const float4*)(g_f + (size_t)row * CH))[t];
    float s = fv.x + fv.y + fv.z + fv.w;
    float q = fv.x*fv.x + fv.y*fv.y + fv.z*fv.z + fv.w*fv.w;
    #pragma unroll
    for (int o = 16; o; o >>= 1) { s += __shfl_xor_sync(~0u, s, o); q += __shfl_xor_sync(~0u, q, o); }
    if ((t & 31) == 0) { sb[t >> 5] = s; sb[8 + (t >> 5)] = q; }
    __syncthreads();
    s = 0.f; q = 0.f;
    #pragma unroll
    for (int i = 0; i < 8; i++) { s += sb[i]; q += sb[8 + i]; }
    float mu1 = s * (1.0f / CH);
    float rs1 = rsqrtf(q * (1.0f / CH) - mu1 * mu1 + 1e-5f);

    float4 xv  = ((const float4*)(x + (size_t)row * CH))[t];
    float4 g1  = ((const float4*)lnfg)[t];
    float4 b1v = ((const float4*)lnfb)[t];
    float4 x1v;
    x1v.x = xv.x + (fv.x - mu1) * rs1 * g1.x + b1v.x;
    x1v.y = xv.y + (fv.y - mu1) * rs1 * g1.y + b1v.y;
    x1v.z = xv.z + (fv.z - mu1) * rs1 * g1.z + b1v.z;
    x1v.w = xv.w + (fv.w - mu1) * rs1 * g1.w + b1v.w;
    ((float4*)(g_x1 + (size_t)row * CH))[t] = x1v;

    __syncthreads();
    s = x1v.x + x1v.y + x1v.z + x1v.w;
    q = x1v.x*x1v.x + x1v.y*x1v.y + x1v.z*x1v.z + x1v.w*x1v.w;
    #pragma unroll
    for (int o = 16; o; o >>= 1) { s += __shfl_xor_sync(~0u, s, o); q += __shfl_xor_sync(~0u, q, o); }
    if ((t & 31) == 0) { sb[t >> 5] = s; sb[8 + (t >> 5)] = q; }
    __syncthreads();
    s = 0.f; q = 0.f;
    #pragma unroll
    for (int i = 0; i < 8; i++) { s += sb[i]; q += sb[8 + i]; }
    float mu2 = s * (1.0f / CH);
    float rs2 = rsqrtf(q * (1.0f / CH) - mu2 * mu2 + 1e-5f);

    float4 g2  = ((const float4*)ln2g)[t];
    float4 b2v = ((const float4*)ln2b)[t];
    __half2 p0, p1;
    p0.x = __float2half_rn((x1v.x - mu2) * rs2 * g2.x + b2v.x);
    p0.y = __float2half_rn((x1v.y - mu2) * rs2 * g2.y + b2v.y);
    p1.x = __float2half_rn((x1v.z - mu2) * rs2 * g2.z + b2v.z);
    p1.y = __float2half_rn((x1v.w - mu2) * rs2 * g2.w + b2v.w);
    __half2* dst = (__half2*)(g_h2 + (size_t)row * CH);
    dst[2 * t] = p0; dst[2 * t + 1] = p1;
}

// ---------------- fp16 mma.sync GEMM: C = epi(A[M,K] @ Bt[N,K]^T) ------------
// 128x128x64 block, 4 warps (64x64 warp tile), 3-stage cp.async, SW128 smem.
// EPI: 0 plain fp32 store, 1 fp16(gelu(.+bias)), 2 fp32 .+bias+resid
template <int EPI, typename OutT>
__global__ void __launch_bounds__(128)
gemm_mma(const __half* __restrict__ A, const __half* __restrict__ Bt,
         OutT* __restrict__ Cout, const float* __restrict__ bias,
         const float* __restrict__ resid, int K, int ldc) {
    constexpr int BK = 64, STG = 3;
    constexpr int TILEB = 128 * 64 * 2;   // 16 KB per operand per stage

    extern __shared__ __align__(128) char smem[];
    uint32_t sbase = smem_u32(smem);

    int tid = threadIdx.x, warp = tid >> 5, lane = tid & 31;
    int wm = warp & 1, wn = warp >> 1;            // 2x2 warp grid, 64x64 tiles
    size_t bm = (size_t)blockIdx.x * 128, bn = (size_t)blockIdx.y * 128;

    float acc[4][8][4];
    #pragma unroll
    for (int i = 0; i < 4; i++)
        #pragma unroll
        for (int j = 0; j < 8; j++)
            #pragma unroll
            for (int e = 0; e < 4; e++) acc[i][j][e] = 0.f;

    auto loadStage = [&](int kt, int s) {
        int kb = kt * BK;
        uint32_t aB = sbase + s * 2 * TILEB;
        uint32_t bB = aB + TILEB;
        const __half* Ap = A + bm * K + kb;
        const __half* Bp = Bt + bn * K + kb;
        #pragma unroll
        for (int i = 0; i < 8; i++) {              // A: 128 rows x 128B
            int f = tid + i * 128;
            int r = f >> 3, c = f & 7;
            cp16(aB + SW128(r * 128 + c * 16), Ap + (size_t)r * K + c * 8);
        }
        #pragma unroll
        for (int i = 0; i < 8; i++) {              // B: 128 rows x 128B
            int f = tid + i * 128;
            int r = f >> 3, c = f & 7;
            cp16(bB + SW128(r * 128 + c * 16), Bp + (size_t)r * K + c * 8);
        }
    };

    int NT = K / BK;                               // 16 or 64
    loadStage(0, 0); CP_COMMIT();
    loadStage(1, 1); CP_COMMIT();

    for (int kt = 0; kt < NT; kt++) {
        if (kt + 2 < NT) {
            loadStage(kt + 2, (kt + 2) % STG);
            CP_COMMIT();
            asm volatile("cp.async.wait_group 2;" ::: "memory");
        } else if (kt + 1 < NT) {
            asm volatile("cp.async.wait_group 1;" ::: "memory");
        } else {
            asm volatile("cp.async.wait_group 0;" ::: "memory");
        }
        __syncthreads();

        uint32_t aS = sbase + (kt % STG) * 2 * TILEB;
        uint32_t bS = aS + TILEB;
        #pragma unroll
        for (int ks = 0; ks < 4; ks++) {
            uint32_t a[4][4], b[8][2];
            #pragma unroll
            for (int mi = 0; mi < 4; mi++) {
                int row  = wm * 64 + mi * 16 + (lane & 15);
                int colh = ks * 16 + (lane >> 4) * 8;
                ldsm4(a[mi], aS + SW128(row * 128 + colh * 2));
            }
            #pragma unroll
            for (int ni = 0; ni < 8; ni++) {
                int row  = wn * 64 + ni * 8 + (lane & 7);
                int colh = ks * 16 + ((lane >> 3) & 1) * 8;
                ldsm2(b[ni], bS + SW128(row * 128 + colh * 2));
            }
            #pragma unroll
            for (int mi = 0; mi < 4; mi++)
                #pragma unroll
                for (int ni = 0; ni < 8; ni++)
                    mma16816(acc[mi][ni], a[mi], b[ni]);
        }
        __syncthreads();
    }

    // direct-register epilogue
    #pragma unroll
    for (int mi = 0; mi < 4; mi++) {
        #pragma unroll
        for (int ni = 0; ni < 8; ni++) {
            size_t gr = bm + wm * 64 + mi * 16 + (lane >> 2);
            int gc = (int)bn + wn * 64 + ni * 8 + (lane & 3) * 2;
            #pragma unroll
            for (int h = 0; h < 2; h++) {          // h=0: rows r, h=1: rows r+8
                size_t row = gr + h * 8;
                float v0 = acc[mi][ni][2 * h + 0];
                float v1 = acc[mi][ni][2 * h + 1];
                if (EPI == 1) {
                    v0 += bias[gc];     v1 += bias[gc + 1];
                    v0 = 0.5f * v0 * (1.0f + erff(v0 * 0.70710678118654752f));
                    v1 = 0.5f * v1 * (1.0f + erff(v1 * 0.70710678118654752f));
                    __half2 hv; hv.x = __float2half_rn(v0); hv.y = __float2half_rn(v1);
                    *(__half2*)((__half*)Cout + row * ldc + gc) = hv;
                } else {
                    if (EPI == 2) {
                        v0 += bias[gc]     + resid[row * ldc + gc];
                        v1 += bias[gc + 1] + resid[row * ldc + gc + 1];
                    }
                    float2 fv; fv.x = v0; fv.y = v1;
                    *(float2*)((float*)Cout + row * ldc + gc) = fv;
                }
            }
        }
    }
}

// ---------------- entry ------------------------------------------------------
extern "C" void kernel_launch(void* const* d_in, const int* in_sizes, int n_in,
                              void* d_out, int out_size) {
    const float* x    = (const float*)d_in[0];
    const float* ln1g = (const float*)d_in[1];
    const float* ln1b = (const float*)d_in[2];
    const float* lnfg = (const float*)d_in[3];
    const float* lnfb = (const float*)d_in[4];
    const float* ln2g = (const float*)d_in[5];
    const float* ln2b = (const float*)d_in[6];
    const float* w1   = (const float*)d_in[7];
    const float* b1   = (const float*)d_in[8];
    const float* w2   = (const float*)d_in[9];
    const float* b2   = (const float*)d_in[10];
    float* out = (float*)d_out;

    __half *ph, *ph2, *pm, *pcos, *pw1t, *pw2t;
    float *pf, *px1;
    cudaGetSymbolAddress((void**)&ph,   g_h);
    cudaGetSymbolAddress((void**)&pf,   g_f);
    cudaGetSymbolAddress((void**)&px1,  g_x1);
    cudaGetSymbolAddress((void**)&ph2,  g_h2);
    cudaGetSymbolAddress((void**)&pm,   g_m);
    cudaGetSymbolAddress((void**)&pcos, g_cosh);
    cudaGetSymbolAddress((void**)&pw1t, g_w1t);
    cudaGetSymbolAddress((void**)&pw2t, g_w2t);

    constexpr int SMEM = 3 * 2 * 128 * 64 * 2;   // 98304 B
    cudaFuncSetAttribute(gemm_mma<0, float>,  cudaFuncAttributeMaxDynamicSharedMemorySize, SMEM);
    cudaFuncSetAttribute(gemm_mma<1, __half>, cudaFuncAttributeMaxDynamicSharedMemorySize, SMEM);
    cudaFuncSetAttribute(gemm_mma<2, float>,  cudaFuncAttributeMaxDynamicSharedMemorySize, SMEM);

    // constants: cos matrix (symmetric, already [N][K]); transposed fp16 weights
    fill_cos_kernel<<<1024, 1024>>>();
    transpose_h<<<dim3(HID / 32, CH / 32), dim3(32, 8)>>>(w1, pw1t, CH, HID);
    transpose_h<<<dim3(CH / 32, HID / 32), dim3(32, 8)>>>(w2, pw2t, HID, CH);
    // h = fp16(ln1(x))
    ln_kernel<<<TOK, 256>>>(x, ln1g, ln1b, ph);
    // f = h @ cos^T
    gemm_mma<0, float><<<dim3(TOK / 128, CH / 128), 128, SMEM>>>(
        ph, pcos, pf, nullptr, nullptr, CH, CH);
    // x1 = x + lnf(f); h2 = fp16(ln2(x1))
    fuse2_kernel<<<TOK, 256>>>(x, lnfg, lnfb, ln2g, ln2b);
    // m = fp16(gelu(h2 @ w1 + b1))
    gemm_mma<1, __half><<<dim3(TOK / 128, HID / 128), 128, SMEM>>>(
        ph2, pw1t, pm, b1, nullptr, CH, HID);
    // out = x1 + m @ w2 + b2
    gemm_mma<2, float><<<dim3(TOK / 128, CH / 128), 128, SMEM>>>(
        pm, pw2t, out, b2, px1, HID, CH);
}